// round 2
// baseline (speedup 1.0000x reference)
#include <cuda_runtime.h>
#include <cstdint>

// ---------------------------------------------------------------------------
// Problem constants
// ---------------------------------------------------------------------------
#define OUT_DIM 4096
#define IN_DIM  4096
#define M_TOTAL 8192                 // 4 * 2048
#define R_DIM   64
#define KX      (IN_DIM + R_DIM)     // 4160 : K of fused GEMM  [x | T] . [W | loraB]^T
#define NBLOCKS (OUT_DIM * IN_DIM / 64)

// Scratch device globals (allocation-free rule)
__device__ float g_X[(size_t)M_TOTAL * KX];   // [8192][4160] : rna_tf32(x) | rna_tf32(2 x A^T)
__device__ float g_W[(size_t)OUT_DIM * KX];   // [4096][4160] : dequant(W)  | rna_tf32(lora_B)
__device__ float g_LA[(size_t)R_DIM * IN_DIM];// [64][4096]   : rna_tf32(lora_A)

__constant__ float c_nf4[16] = {
    -1.0f, -0.6961928009986877f, -0.5250730514526367f, -0.39491748809814453f,
    -0.28444138169288635f, -0.18477343022823334f, -0.09105003625154495f, 0.0f,
    0.07958029955625534f, 0.16093020141124725f, 0.24611230194568634f, 0.33791524171829224f,
    0.44070982933044434f, 0.5626170039176941f, 0.7229568362236023f, 1.0f};

// ---------------------------------------------------------------------------
// Helpers (plain sm_80-level PTX only — toolchain targets sm_103 WITHOUT 'a')
// ---------------------------------------------------------------------------
__device__ __forceinline__ float rna_tf32(float v) {
    uint32_t r;
    asm("cvt.rna.tf32.f32 %0, %1;" : "=r"(r) : "f"(v));
    return __uint_as_float(r);
}

__device__ __forceinline__ void cp_async16(void* smem_dst, const void* gptr) {
    uint32_t s = (uint32_t)__cvta_generic_to_shared(smem_dst);
    asm volatile("cp.async.cg.shared.global [%0], [%1], 16;" :: "r"(s), "l"(gptr));
}
__device__ __forceinline__ void cp_commit() {
    asm volatile("cp.async.commit_group;" ::: "memory");
}
template <int N>
__device__ __forceinline__ void cp_wait() {
    asm volatile("cp.async.wait_group %0;" :: "n"(N) : "memory");
}

// D += A(16x8, row) * B(8x8, col) ; tf32 operands as raw b32
__device__ __forceinline__ void mma_tf32(float* c, const uint32_t* a, const uint32_t* b) {
    asm volatile(
        "mma.sync.aligned.m16n8k8.row.col.f32.tf32.tf32.f32 "
        "{%0,%1,%2,%3}, {%4,%5,%6,%7}, {%8,%9}, {%0,%1,%2,%3};"
        : "+f"(c[0]), "+f"(c[1]), "+f"(c[2]), "+f"(c[3])
        : "r"(a[0]), "r"(a[1]), "r"(a[2]), "r"(a[3]), "r"(b[0]), "r"(b[1]));
}

// ---------------------------------------------------------------------------
// Prep kernels
// ---------------------------------------------------------------------------
__global__ void dequant_kernel(const int* __restrict__ codes, const float* __restrict__ absmax) {
    int b = blockIdx.x * blockDim.x + threadIdx.x;
    if (b >= NBLOCKS) return;
    float s = absmax[b];
    const int4* c4 = reinterpret_cast<const int4*>(codes) + (size_t)b * 16;
    float4* o4 = reinterpret_cast<float4*>(g_W + (size_t)(b >> 6) * KX + (b & 63) * 64);
#pragma unroll
    for (int i = 0; i < 16; i++) {
        int4 c = c4[i];
        float4 o;
        o.x = rna_tf32(c_nf4[c.x & 15] * s);
        o.y = rna_tf32(c_nf4[c.y & 15] * s);
        o.z = rna_tf32(c_nf4[c.z & 15] * s);
        o.w = rna_tf32(c_nf4[c.w & 15] * s);
        o4[i] = o;
    }
}

// x [8192][4096] -> g_X [8192][4160] (cols 0..4095), tf32-rounded
__global__ void roundx_kernel(const float4* __restrict__ x) {
    const int n4 = M_TOTAL * IN_DIM / 4;
    float4* o = reinterpret_cast<float4*>(g_X);
    for (int i = blockIdx.x * blockDim.x + threadIdx.x; i < n4; i += gridDim.x * blockDim.x) {
        int m = i >> 10, k4 = i & 1023;          // 1024 float4 per source row
        float4 v = x[i];
        v.x = rna_tf32(v.x); v.y = rna_tf32(v.y); v.z = rna_tf32(v.z); v.w = rna_tf32(v.w);
        o[(size_t)m * (KX / 4) + k4] = v;
    }
}

// lora_A [64][4096] -> g_LA (tf32-rounded, contiguous)
__global__ void round_la_kernel(const float4* __restrict__ la) {
    int i = blockIdx.x * blockDim.x + threadIdx.x;
    if (i >= R_DIM * IN_DIM / 4) return;
    float4 v = la[i];
    v.x = rna_tf32(v.x); v.y = rna_tf32(v.y); v.z = rna_tf32(v.z); v.w = rna_tf32(v.w);
    reinterpret_cast<float4*>(g_LA)[i] = v;
}

// lora_B [4096][64] -> g_W cols 4096..4159 (tf32-rounded)
__global__ void round_lb_kernel(const float4* __restrict__ lb) {
    int i = blockIdx.x * blockDim.x + threadIdx.x;
    if (i >= OUT_DIM * R_DIM / 4) return;
    int n = i >> 4, r4 = i & 15;                 // 16 float4 per row of lora_B
    float4 v = lb[i];
    v.x = rna_tf32(v.x); v.y = rna_tf32(v.y); v.z = rna_tf32(v.z); v.w = rna_tf32(v.w);
    reinterpret_cast<float4*>(g_W)[(size_t)n * (KX / 4) + (IN_DIM / 4) + r4] = v;
}

// ---------------------------------------------------------------------------
// Multistage tf32 mma.sync GEMM :  C[BMxBN] = A[BM,K] @ B[BN,K]^T
//   BM=128, BK=32 floats, 4 stages cp.async, 256 threads (warps 2M x 4N),
//   warp tile 64 x WN.  smem rows padded to 36 floats (conflict-free frags).
//   TMODE: C = rna_tf32(2 * acc)   (T = 2 x A^T, feeding the fused GEMM)
// ---------------------------------------------------------------------------
template <int BN, int WN, bool TMODE>
__global__ __launch_bounds__(256, 1)
void gemm_mma(const float* __restrict__ A, int lda,
              const float* __restrict__ B, int ldb,
              float* __restrict__ C, int ldc, int nk) {
    constexpr int BM = 128, SA = 36, STAGES = 4;
    constexpr int MT = 4;           // 64/16 m-tiles per warp
    constexpr int NT = WN / 8;      // n-tiles per warp
    constexpr int ACH = 4;          // A: 1024 16B-chunks / 256 thr
    constexpr int BCH = BN * 8 / 256;

    extern __shared__ float smem[];
    float* sA = smem;                               // [STAGES][BM*SA]
    float* sB = smem + STAGES * BM * SA;            // [STAGES][BN*SA]

    const int tid = threadIdx.x, lane = tid & 31, wid = tid >> 5;
    const int wm = wid & 1, wn = wid >> 1;          // 2 x 4 warp grid
    const int m0 = blockIdx.y * BM, n0 = blockIdx.x * BN;
    const int lr = lane >> 2, lc = lane & 3;

    const float* gA = A + (size_t)m0 * lda;
    const float* gB = B + (size_t)n0 * ldb;

    // chunk -> (row, col16) decomposition, fixed per thread
    float c[MT][NT][4];
#pragma unroll
    for (int mt = 0; mt < MT; mt++)
#pragma unroll
        for (int nt = 0; nt < NT; nt++)
#pragma unroll
            for (int q = 0; q < 4; q++) c[mt][nt][q] = 0.0f;

    auto load_stage = [&](int s, int kt) {
        const int kk = kt * 32;
        float* dA = sA + s * BM * SA;
        float* dB = sB + s * BN * SA;
#pragma unroll
        for (int i = 0; i < ACH; i++) {
            int ch = tid + 256 * i, row = ch >> 3, col = (ch & 7) * 4;
            cp_async16(dA + row * SA + col, gA + (size_t)row * lda + kk + col);
        }
#pragma unroll
        for (int i = 0; i < BCH; i++) {
            int ch = tid + 256 * i, row = ch >> 3, col = (ch & 7) * 4;
            cp_async16(dB + row * SA + col, gB + (size_t)row * ldb + kk + col);
        }
    };

    auto compute_stage = [&](int s) {
        const uint32_t* ab = reinterpret_cast<const uint32_t*>(sA + s * BM * SA + (wm * 64) * SA);
        const uint32_t* bb = reinterpret_cast<const uint32_t*>(sB + s * BN * SA + (wn * WN) * SA);
#pragma unroll
        for (int ks = 0; ks < 4; ks++) {
            uint32_t af[MT][4], bf[NT][2];
#pragma unroll
            for (int mt = 0; mt < MT; mt++) {
                const uint32_t* p = ab + (mt * 16 + lr) * SA + ks * 8 + lc;
                af[mt][0] = p[0];
                af[mt][1] = p[8 * SA];
                af[mt][2] = p[4];
                af[mt][3] = p[8 * SA + 4];
            }
#pragma unroll
            for (int nt = 0; nt < NT; nt++) {
                const uint32_t* p = bb + (nt * 8 + lr) * SA + ks * 8 + lc;
                bf[nt][0] = p[0];
                bf[nt][1] = p[4];
            }
#pragma unroll
            for (int mt = 0; mt < MT; mt++)
#pragma unroll
                for (int nt = 0; nt < NT; nt++) mma_tf32(c[mt][nt], af[mt], bf[nt]);
        }
    };

    // Prologue: fill 3 stages
    load_stage(0, 0); cp_commit();
    load_stage(1, 1); cp_commit();
    load_stage(2, 2); cp_commit();
    cp_wait<2>();
    __syncthreads();

    for (int kt = 0; kt < nk; kt++) {
        int ls = kt + 3;
        if (ls < nk) load_stage(ls & 3, ls);
        cp_commit();
        compute_stage(kt & 3);
        cp_wait<2>();
        __syncthreads();
    }

    // Epilogue
#pragma unroll
    for (int mt = 0; mt < MT; mt++) {
        int r0 = m0 + wm * 64 + mt * 16 + lr;
#pragma unroll
        for (int nt = 0; nt < NT; nt++) {
            int cc = n0 + wn * WN + nt * 8 + 2 * lc;
            float2 v0 = make_float2(c[mt][nt][0], c[mt][nt][1]);
            float2 v1 = make_float2(c[mt][nt][2], c[mt][nt][3]);
            if (TMODE) {
                v0.x = rna_tf32(2.0f * v0.x); v0.y = rna_tf32(2.0f * v0.y);
                v1.x = rna_tf32(2.0f * v1.x); v1.y = rna_tf32(2.0f * v1.y);
            }
            *reinterpret_cast<float2*>(&C[(size_t)r0 * ldc + cc]) = v0;
            *reinterpret_cast<float2*>(&C[(size_t)(r0 + 8) * ldc + cc]) = v1;
        }
    }
}

// ---------------------------------------------------------------------------
// Host
// ---------------------------------------------------------------------------
extern "C" void kernel_launch(void* const* d_in, const int* in_sizes, int n_in,
                              void* d_out, int out_size) {
    const float* x      = (const float*)d_in[0];
    const float* lora_A = (const float*)d_in[1];
    const float* lora_B = (const float*)d_in[2];
    const float* absmax = (const float*)d_in[3];
    const int*   codes  = (const int*)d_in[4];
    float* out = (float*)d_out;

    void *pX, *pW, *pLA;
    cudaGetSymbolAddress(&pX, g_X);
    cudaGetSymbolAddress(&pW, g_W);
    cudaGetSymbolAddress(&pLA, g_LA);

    constexpr int SMEM_MAIN = 4 * (128 + 128) * 36 * 4;   // 147456
    constexpr int SMEM_T    = 4 * (128 + 64) * 36 * 4;    // 110592
    static bool attr_done = false;
    if (!attr_done) {
        cudaFuncSetAttribute(gemm_mma<128, 32, false>,
                             cudaFuncAttributeMaxDynamicSharedMemorySize, SMEM_MAIN);
        cudaFuncSetAttribute(gemm_mma<64, 16, true>,
                             cudaFuncAttributeMaxDynamicSharedMemorySize, SMEM_T);
        attr_done = true;
    }

    // 1) prep: dequant W, round x / lora_A / lora_B to tf32
    dequant_kernel<<<NBLOCKS / 256, 256>>>(codes, absmax);
    roundx_kernel<<<8192, 256>>>((const float4*)x);
    round_la_kernel<<<(R_DIM * IN_DIM / 4) / 256, 256>>>((const float4*)lora_A);
    round_lb_kernel<<<(OUT_DIM * R_DIM / 4) / 256, 256>>>((const float4*)lora_B);

    // 2) T = rna_tf32(2 * x @ lora_A^T)  -> g_X cols 4096..4159
    gemm_mma<64, 16, true><<<dim3(1, M_TOTAL / 128), 256, SMEM_T>>>(
        (const float*)pX, KX, (const float*)pLA, IN_DIM,
        (float*)pX + IN_DIM, KX, IN_DIM / 32);

    // 3) out = [x|T] @ [W|loraB]^T   (K = 4160)
    gemm_mma<128, 32, false><<<dim3(OUT_DIM / 128, M_TOTAL / 128), 256, SMEM_MAIN>>>(
        (const float*)pX, KX, (const float*)pW, KX,
        out, OUT_DIM, KX / 32);
}

// round 3
// speedup vs baseline: 1.1774x; 1.1774x over previous
#include <cuda_runtime.h>
#include <cstdint>

// ---------------------------------------------------------------------------
// Problem constants
// ---------------------------------------------------------------------------
#define OUT_DIM 4096
#define IN_DIM  4096
#define M_TOTAL 8192                 // 4 * 2048
#define R_DIM   64
#define KX      (IN_DIM + R_DIM)     // 4160 : K of fused GEMM  [x | T] . [W | loraB]^T
#define NBLOCKS (OUT_DIM * IN_DIM / 64)

// Scratch device globals (allocation-free rule)
__device__ float g_X[(size_t)M_TOTAL * KX];   // [8192][4160] : rna_tf32(x) | rna_tf32(2 x A^T)
__device__ float g_W[(size_t)OUT_DIM * KX];   // [4096][4160] : dequant(W)  | rna_tf32(lora_B)
__device__ float g_LA[(size_t)R_DIM * IN_DIM];// [64][4096]   : rna_tf32(lora_A)

__constant__ float c_nf4[16] = {
    -1.0f, -0.6961928009986877f, -0.5250730514526367f, -0.39491748809814453f,
    -0.28444138169288635f, -0.18477343022823334f, -0.09105003625154495f, 0.0f,
    0.07958029955625534f, 0.16093020141124725f, 0.24611230194568634f, 0.33791524171829224f,
    0.44070982933044434f, 0.5626170039176941f, 0.7229568362236023f, 1.0f};

// ---------------------------------------------------------------------------
// Helpers (plain sm_80-level PTX only — toolchain targets sm_103 WITHOUT 'a')
// ---------------------------------------------------------------------------
__device__ __forceinline__ float rna_tf32(float v) {
    uint32_t r;
    asm("cvt.rna.tf32.f32 %0, %1;" : "=r"(r) : "f"(v));
    return __uint_as_float(r);
}

__device__ __forceinline__ void cp_async16(void* smem_dst, const void* gptr) {
    uint32_t s = (uint32_t)__cvta_generic_to_shared(smem_dst);
    asm volatile("cp.async.cg.shared.global [%0], [%1], 16;" :: "r"(s), "l"(gptr));
}
__device__ __forceinline__ void cp_commit() {
    asm volatile("cp.async.commit_group;" ::: "memory");
}
template <int N>
__device__ __forceinline__ void cp_wait() {
    asm volatile("cp.async.wait_group %0;" :: "n"(N) : "memory");
}

// D += A(16x8, row) * B(8x8, col) ; tf32 operands as raw b32
__device__ __forceinline__ void mma_tf32(float* c, const uint32_t* a, const uint32_t* b) {
    asm volatile(
        "mma.sync.aligned.m16n8k8.row.col.f32.tf32.tf32.f32 "
        "{%0,%1,%2,%3}, {%4,%5,%6,%7}, {%8,%9}, {%0,%1,%2,%3};"
        : "+f"(c[0]), "+f"(c[1]), "+f"(c[2]), "+f"(c[3])
        : "r"(a[0]), "r"(a[1]), "r"(a[2]), "r"(a[3]), "r"(b[0]), "r"(b[1]));
}

// ---------------------------------------------------------------------------
// Fused prep kernel (ONE launch): dequant W, round x / lora_A / lora_B
//   blockIdx partition: [0,1024) dequant | [1024,3072) roundx
//                       [3072,3328) round_la | [3328,3584) round_lb
// ---------------------------------------------------------------------------
__global__ __launch_bounds__(256)
void prep_kernel(const float4* __restrict__ x,
                 const float4* __restrict__ lora_A,
                 const float4* __restrict__ lora_B,
                 const float* __restrict__ absmax,
                 const int* __restrict__ codes) {
    const int b = blockIdx.x;
    const int tid = threadIdx.x;
    if (b < 1024) {
        // NF4 dequant: one nf4-block (64 values) per thread
        int blk = b * 256 + tid;
        float s = absmax[blk];
        const int4* c4 = reinterpret_cast<const int4*>(codes) + (size_t)blk * 16;
        float4* o4 = reinterpret_cast<float4*>(g_W + (size_t)(blk >> 6) * KX + (blk & 63) * 64);
#pragma unroll
        for (int i = 0; i < 16; i++) {
            int4 c = c4[i];
            float4 o;
            o.x = rna_tf32(c_nf4[c.x & 15] * s);
            o.y = rna_tf32(c_nf4[c.y & 15] * s);
            o.z = rna_tf32(c_nf4[c.z & 15] * s);
            o.w = rna_tf32(c_nf4[c.w & 15] * s);
            o4[i] = o;
        }
    } else if (b < 3072) {
        // round x -> g_X cols [0,4096)
        const int n4 = M_TOTAL * IN_DIM / 4;
        float4* o = reinterpret_cast<float4*>(g_X);
        for (int i = (b - 1024) * 256 + tid; i < n4; i += 2048 * 256) {
            int m = i >> 10, k4 = i & 1023;
            float4 v = x[i];
            v.x = rna_tf32(v.x); v.y = rna_tf32(v.y);
            v.z = rna_tf32(v.z); v.w = rna_tf32(v.w);
            o[(size_t)m * (KX / 4) + k4] = v;
        }
    } else if (b < 3328) {
        int i = (b - 3072) * 256 + tid;          // 65536 float4
        float4 v = lora_A[i];
        v.x = rna_tf32(v.x); v.y = rna_tf32(v.y);
        v.z = rna_tf32(v.z); v.w = rna_tf32(v.w);
        reinterpret_cast<float4*>(g_LA)[i] = v;
    } else {
        int i = (b - 3328) * 256 + tid;          // 65536 float4
        int n = i >> 4, r4 = i & 15;
        float4 v = lora_B[i];
        v.x = rna_tf32(v.x); v.y = rna_tf32(v.y);
        v.z = rna_tf32(v.z); v.w = rna_tf32(v.w);
        reinterpret_cast<float4*>(g_W)[(size_t)n * (KX / 4) + (IN_DIM / 4) + r4] = v;
    }
}

// ---------------------------------------------------------------------------
// Multistage tf32 mma.sync GEMM :  C[BMxBN] = A[BM,K] @ B[BN,K]^T
//   4 stages cp.async, 256 threads, WM x WN warp grid, smem rows 36 floats.
//   SWIZ: 1-D grid, grouped rasterization (GROUP_M m-blocks per column walk)
//   TMODE: C = rna_tf32(2 * acc)
// ---------------------------------------------------------------------------
template <int BM, int BN, int WM, int WN, bool TMODE, bool SWIZ>
__global__ __launch_bounds__(256, 1)
void gemm_mma(const float* __restrict__ A, int lda,
              const float* __restrict__ B, int ldb,
              float* __restrict__ C, int ldc, int nk, int nblk) {
    constexpr int SA = 36, STAGES = 4;
    constexpr int WTM = BM / WM, WTN = BN / WN;   // warp tile
    constexpr int MT = WTM / 16, NT = WTN / 8;
    constexpr int ACH = BM * 8 / 256;             // 16B chunks per thread (A)
    constexpr int BCH = BN * 8 / 256;

    extern __shared__ float smem[];
    float* sA = smem;                              // [STAGES][BM*SA]
    float* sB = smem + STAGES * BM * SA;           // [STAGES][BN*SA]

    const int tid = threadIdx.x, lane = tid & 31, wid = tid >> 5;
    const int wm = wid % WM, wn = wid / WM;
    const int lr = lane >> 2, lc = lane & 3;

    int m0, n0;
    if (SWIZ) {
        constexpr int GROUP = 8;
        int bid = blockIdx.x;
        int grp = bid / (GROUP * nblk);
        int rem = bid % (GROUP * nblk);
        m0 = (grp * GROUP + rem % GROUP) * BM;
        n0 = (rem / GROUP) * BN;
    } else {
        m0 = blockIdx.y * BM;
        n0 = blockIdx.x * BN;
    }

    const float* gA = A + (size_t)m0 * lda;
    const float* gB = B + (size_t)n0 * ldb;

    float c[MT][NT][4];
#pragma unroll
    for (int mt = 0; mt < MT; mt++)
#pragma unroll
        for (int nt = 0; nt < NT; nt++)
#pragma unroll
            for (int q = 0; q < 4; q++) c[mt][nt][q] = 0.0f;

    auto load_stage = [&](int s, int kt) {
        const int kk = kt * 32;
        float* dA = sA + s * BM * SA;
        float* dB = sB + s * BN * SA;
#pragma unroll
        for (int i = 0; i < ACH; i++) {
            int ch = tid + 256 * i, row = ch >> 3, col = (ch & 7) * 4;
            cp_async16(dA + row * SA + col, gA + (size_t)row * lda + kk + col);
        }
#pragma unroll
        for (int i = 0; i < BCH; i++) {
            int ch = tid + 256 * i, row = ch >> 3, col = (ch & 7) * 4;
            cp_async16(dB + row * SA + col, gB + (size_t)row * ldb + kk + col);
        }
    };

    auto compute_stage = [&](int s) {
        const uint32_t* ab = reinterpret_cast<const uint32_t*>(sA + s * BM * SA + (wm * WTM) * SA);
        const uint32_t* bb = reinterpret_cast<const uint32_t*>(sB + s * BN * SA + (wn * WTN) * SA);
#pragma unroll
        for (int ks = 0; ks < 4; ks++) {
            uint32_t af[MT][4], bf[NT][2];
#pragma unroll
            for (int mt = 0; mt < MT; mt++) {
                const uint32_t* p = ab + (mt * 16 + lr) * SA + ks * 8 + lc;
                af[mt][0] = p[0];
                af[mt][1] = p[8 * SA];
                af[mt][2] = p[4];
                af[mt][3] = p[8 * SA + 4];
            }
#pragma unroll
            for (int nt = 0; nt < NT; nt++) {
                const uint32_t* p = bb + (nt * 8 + lr) * SA + ks * 8 + lc;
                bf[nt][0] = p[0];
                bf[nt][1] = p[4];
            }
#pragma unroll
            for (int mt = 0; mt < MT; mt++)
#pragma unroll
                for (int nt = 0; nt < NT; nt++) mma_tf32(c[mt][nt], af[mt], bf[nt]);
        }
    };

    // Prologue: fill 3 stages
    load_stage(0, 0); cp_commit();
    load_stage(1, 1); cp_commit();
    load_stage(2, 2); cp_commit();
    cp_wait<2>();
    __syncthreads();

    for (int kt = 0; kt < nk; kt++) {
        int ls = kt + 3;
        if (ls < nk) load_stage(ls & 3, ls);
        cp_commit();
        compute_stage(kt & 3);
        cp_wait<2>();
        __syncthreads();
    }

    // Epilogue
#pragma unroll
    for (int mt = 0; mt < MT; mt++) {
        int r0 = m0 + wm * WTM + mt * 16 + lr;
#pragma unroll
        for (int nt = 0; nt < NT; nt++) {
            int cc = n0 + wn * WTN + nt * 8 + 2 * lc;
            float2 v0 = make_float2(c[mt][nt][0], c[mt][nt][1]);
            float2 v1 = make_float2(c[mt][nt][2], c[mt][nt][3]);
            if (TMODE) {
                v0.x = rna_tf32(2.0f * v0.x); v0.y = rna_tf32(2.0f * v0.y);
                v1.x = rna_tf32(2.0f * v1.x); v1.y = rna_tf32(2.0f * v1.y);
            }
            *reinterpret_cast<float2*>(&C[(size_t)r0 * ldc + cc]) = v0;
            *reinterpret_cast<float2*>(&C[(size_t)(r0 + 8) * ldc + cc]) = v1;
        }
    }
}

// ---------------------------------------------------------------------------
// Host
// ---------------------------------------------------------------------------
extern "C" void kernel_launch(void* const* d_in, const int* in_sizes, int n_in,
                              void* d_out, int out_size) {
    const float* x      = (const float*)d_in[0];
    const float* lora_A = (const float*)d_in[1];
    const float* lora_B = (const float*)d_in[2];
    const float* absmax = (const float*)d_in[3];
    const int*   codes  = (const int*)d_in[4];
    float* out = (float*)d_out;

    void *pX, *pW, *pLA;
    cudaGetSymbolAddress(&pX, g_X);
    cudaGetSymbolAddress(&pW, g_W);
    cudaGetSymbolAddress(&pLA, g_LA);

    // main: BM=256 BN=128, 4 stages -> 4*(256+128)*36*4 = 221184 B
    constexpr int SMEM_MAIN = 4 * (256 + 128) * 36 * 4;
    // T   : BM=128 BN=64  -> 4*(128+64)*36*4 = 110592 B
    constexpr int SMEM_T    = 4 * (128 + 64) * 36 * 4;
    static bool attr_done = false;
    if (!attr_done) {
        cudaFuncSetAttribute((const void*)gemm_mma<256, 128, 4, 2, false, true>,
                             cudaFuncAttributeMaxDynamicSharedMemorySize, SMEM_MAIN);
        cudaFuncSetAttribute((const void*)gemm_mma<128, 64, 4, 2, true, false>,
                             cudaFuncAttributeMaxDynamicSharedMemorySize, SMEM_T);
        attr_done = true;
    }

    // 1) fused prep (one launch)
    prep_kernel<<<3584, 256>>>((const float4*)x, (const float4*)lora_A,
                               (const float4*)lora_B, absmax, codes);

    // 2) T = rna_tf32(2 * x @ lora_A^T)  -> g_X cols 4096..4159
    gemm_mma<128, 64, 4, 2, true, false><<<dim3(1, M_TOTAL / 128), 256, SMEM_T>>>(
        (const float*)pX, KX, (const float*)pLA, IN_DIM,
        (float*)pX + IN_DIM, KX, IN_DIM / 32, 1);

    // 3) out = [x|T] @ [W|loraB]^T   (K = 4160), swizzled 1-D grid
    constexpr int NBLK = OUT_DIM / 128;           // 32 n-blocks
    constexpr int MBLK = M_TOTAL / 256;           // 32 m-blocks
    gemm_mma<256, 128, 4, 2, false, true><<<MBLK * NBLK, 256, SMEM_MAIN>>>(
        (const float*)pX, KX, (const float*)pW, KX,
        out, OUT_DIM, KX / 32, NBLK);
}

// round 4
// speedup vs baseline: 1.1982x; 1.0177x over previous
#include <cuda_runtime.h>
#include <cstdint>

// ---------------------------------------------------------------------------
// Problem constants
// ---------------------------------------------------------------------------
#define OUT_DIM 4096
#define IN_DIM  4096
#define M_TOTAL 8192                 // 4 * 2048
#define R_DIM   64
#define KX      (IN_DIM + R_DIM)     // 4160 : K of fused GEMM  [x | T] . [W | loraB]^T
#define NBLOCKS (OUT_DIM * IN_DIM / 64)

// Scratch device globals (allocation-free rule)
__device__ float g_X[(size_t)M_TOTAL * KX];   // [8192][4160] : rna_tf32(x) | rna_tf32(2 x A^T)
__device__ float g_W[(size_t)OUT_DIM * KX];   // [4096][4160] : dequant(W)  | rna_tf32(lora_B)
__device__ float g_LA[(size_t)R_DIM * IN_DIM];// [64][4096]   : rna_tf32(lora_A)

__constant__ float c_nf4[16] = {
    -1.0f, -0.6961928009986877f, -0.5250730514526367f, -0.39491748809814453f,
    -0.28444138169288635f, -0.18477343022823334f, -0.09105003625154495f, 0.0f,
    0.07958029955625534f, 0.16093020141124725f, 0.24611230194568634f, 0.33791524171829224f,
    0.44070982933044434f, 0.5626170039176941f, 0.7229568362236023f, 1.0f};

// ---------------------------------------------------------------------------
// Helpers (plain sm_80-level PTX only — toolchain targets sm_103 WITHOUT 'a')
// ---------------------------------------------------------------------------
__device__ __forceinline__ float rna_tf32(float v) {
    uint32_t r;
    asm("cvt.rna.tf32.f32 %0, %1;" : "=r"(r) : "f"(v));
    return __uint_as_float(r);
}

__device__ __forceinline__ void cp_async16(void* smem_dst, const void* gptr) {
    uint32_t s = (uint32_t)__cvta_generic_to_shared(smem_dst);
    asm volatile("cp.async.cg.shared.global [%0], [%1], 16;" :: "r"(s), "l"(gptr));
}
__device__ __forceinline__ void cp_commit() {
    asm volatile("cp.async.commit_group;" ::: "memory");
}
template <int N>
__device__ __forceinline__ void cp_wait() {
    asm volatile("cp.async.wait_group %0;" :: "n"(N) : "memory");
}

// D += A(16x8, row) * B(8x8, col) ; tf32 operands as raw b32
__device__ __forceinline__ void mma_tf32(float* c, const uint32_t* a, const uint32_t* b) {
    asm volatile(
        "mma.sync.aligned.m16n8k8.row.col.f32.tf32.tf32.f32 "
        "{%0,%1,%2,%3}, {%4,%5,%6,%7}, {%8,%9}, {%0,%1,%2,%3};"
        : "+f"(c[0]), "+f"(c[1]), "+f"(c[2]), "+f"(c[3])
        : "r"(a[0]), "r"(a[1]), "r"(a[2]), "r"(a[3]), "r"(b[0]), "r"(b[1]));
}

// ---------------------------------------------------------------------------
// Fused prep kernel (ONE launch): dequant W, round x / lora_A / lora_B
// ---------------------------------------------------------------------------
__global__ __launch_bounds__(256)
void prep_kernel(const float4* __restrict__ x,
                 const float4* __restrict__ lora_A,
                 const float4* __restrict__ lora_B,
                 const float* __restrict__ absmax,
                 const int* __restrict__ codes) {
    const int b = blockIdx.x;
    const int tid = threadIdx.x;
    if (b < 1024) {
        int blk = b * 256 + tid;
        float s = absmax[blk];
        const int4* c4 = reinterpret_cast<const int4*>(codes) + (size_t)blk * 16;
        float4* o4 = reinterpret_cast<float4*>(g_W + (size_t)(blk >> 6) * KX + (blk & 63) * 64);
#pragma unroll
        for (int i = 0; i < 16; i++) {
            int4 c = c4[i];
            float4 o;
            o.x = rna_tf32(c_nf4[c.x & 15] * s);
            o.y = rna_tf32(c_nf4[c.y & 15] * s);
            o.z = rna_tf32(c_nf4[c.z & 15] * s);
            o.w = rna_tf32(c_nf4[c.w & 15] * s);
            o4[i] = o;
        }
    } else if (b < 3072) {
        const int n4 = M_TOTAL * IN_DIM / 4;
        float4* o = reinterpret_cast<float4*>(g_X);
        for (int i = (b - 1024) * 256 + tid; i < n4; i += 2048 * 256) {
            int m = i >> 10, k4 = i & 1023;
            float4 v = x[i];
            v.x = rna_tf32(v.x); v.y = rna_tf32(v.y);
            v.z = rna_tf32(v.z); v.w = rna_tf32(v.w);
            o[(size_t)m * (KX / 4) + k4] = v;
        }
    } else if (b < 3328) {
        int i = (b - 3072) * 256 + tid;          // 65536 float4
        float4 v = lora_A[i];
        v.x = rna_tf32(v.x); v.y = rna_tf32(v.y);
        v.z = rna_tf32(v.z); v.w = rna_tf32(v.w);
        reinterpret_cast<float4*>(g_LA)[i] = v;
    } else {
        int i = (b - 3328) * 256 + tid;          // 65536 float4
        int n = i >> 4, r4 = i & 15;
        float4 v = lora_B[i];
        v.x = rna_tf32(v.x); v.y = rna_tf32(v.y);
        v.z = rna_tf32(v.z); v.w = rna_tf32(v.w);
        reinterpret_cast<float4*>(g_W)[(size_t)n * (KX / 4) + (IN_DIM / 4) + r4] = v;
    }
}

// ---------------------------------------------------------------------------
// Multistage tf32 mma.sync GEMM :  C[BMxBN] = A[BM,K] @ B[BN,K]^T
//   STAGES-deep cp.async pipeline, 256 threads, WM x WN warp grid,
//   smem rows 36 floats (conflict-free fragment loads).
//   MINCTAS: occupancy target (2 CTAs/SM for the main GEMM -> 16 warps/SM).
//   SWIZ: 1-D grid, grouped rasterization. TMODE: C = rna_tf32(2 * acc).
// ---------------------------------------------------------------------------
template <int BM, int BN, int WM, int WN, int STAGES, int MINCTAS, bool TMODE, bool SWIZ>
__global__ __launch_bounds__(256, MINCTAS)
void gemm_mma(const float* __restrict__ A, int lda,
              const float* __restrict__ B, int ldb,
              float* __restrict__ C, int ldc, int nk, int nblk) {
    constexpr int SA = 36;
    constexpr int WTM = BM / WM, WTN = BN / WN;   // warp tile
    constexpr int MT = WTM / 16, NT = WTN / 8;
    constexpr int ACH = BM * 8 / 256;             // 16B chunks per thread (A)
    constexpr int BCH = BN * 8 / 256;

    extern __shared__ float smem[];
    float* sA = smem;                              // [STAGES][BM*SA]
    float* sB = smem + STAGES * BM * SA;           // [STAGES][BN*SA]

    const int tid = threadIdx.x, lane = tid & 31, wid = tid >> 5;
    const int wm = wid % WM, wn = wid / WM;
    const int lr = lane >> 2, lc = lane & 3;

    int m0, n0;
    if (SWIZ) {
        constexpr int GROUP = 8;
        int bid = blockIdx.x;
        int grp = bid / (GROUP * nblk);
        int rem = bid % (GROUP * nblk);
        m0 = (grp * GROUP + rem % GROUP) * BM;
        n0 = (rem / GROUP) * BN;
    } else {
        m0 = blockIdx.y * BM;
        n0 = blockIdx.x * BN;
    }

    const float* gA = A + (size_t)m0 * lda;
    const float* gB = B + (size_t)n0 * ldb;

    float c[MT][NT][4];
#pragma unroll
    for (int mt = 0; mt < MT; mt++)
#pragma unroll
        for (int nt = 0; nt < NT; nt++)
#pragma unroll
            for (int q = 0; q < 4; q++) c[mt][nt][q] = 0.0f;

    auto load_stage = [&](int s, int kt) {
        const int kk = kt * 32;
        float* dA = sA + s * BM * SA;
        float* dB = sB + s * BN * SA;
#pragma unroll
        for (int i = 0; i < ACH; i++) {
            int ch = tid + 256 * i, row = ch >> 3, col = (ch & 7) * 4;
            cp_async16(dA + row * SA + col, gA + (size_t)row * lda + kk + col);
        }
#pragma unroll
        for (int i = 0; i < BCH; i++) {
            int ch = tid + 256 * i, row = ch >> 3, col = (ch & 7) * 4;
            cp_async16(dB + row * SA + col, gB + (size_t)row * ldb + kk + col);
        }
    };

    auto compute_stage = [&](int s) {
        const uint32_t* ab = reinterpret_cast<const uint32_t*>(sA + s * BM * SA + (wm * WTM) * SA);
        const uint32_t* bb = reinterpret_cast<const uint32_t*>(sB + s * BN * SA + (wn * WTN) * SA);
#pragma unroll
        for (int ks = 0; ks < 4; ks++) {
            uint32_t af[MT][4], bf[NT][2];
#pragma unroll
            for (int mt = 0; mt < MT; mt++) {
                const uint32_t* p = ab + (mt * 16 + lr) * SA + ks * 8 + lc;
                af[mt][0] = p[0];
                af[mt][1] = p[8 * SA];
                af[mt][2] = p[4];
                af[mt][3] = p[8 * SA + 4];
            }
#pragma unroll
            for (int nt = 0; nt < NT; nt++) {
                const uint32_t* p = bb + (nt * 8 + lr) * SA + ks * 8 + lc;
                bf[nt][0] = p[0];
                bf[nt][1] = p[4];
            }
#pragma unroll
            for (int mt = 0; mt < MT; mt++)
#pragma unroll
                for (int nt = 0; nt < NT; nt++) mma_tf32(c[mt][nt], af[mt], bf[nt]);
        }
    };

    // Prologue: fill STAGES-1 stages
#pragma unroll
    for (int s = 0; s < STAGES - 1; s++) {
        load_stage(s, s);
        cp_commit();
    }
    cp_wait<STAGES - 2>();
    __syncthreads();

    for (int kt = 0; kt < nk; kt++) {
        int ls = kt + STAGES - 1;
        if (ls < nk) load_stage(ls % STAGES, ls);
        cp_commit();
        compute_stage(kt % STAGES);
        cp_wait<STAGES - 2>();
        __syncthreads();
    }

    // Epilogue
#pragma unroll
    for (int mt = 0; mt < MT; mt++) {
        int r0 = m0 + wm * WTM + mt * 16 + lr;
#pragma unroll
        for (int nt = 0; nt < NT; nt++) {
            int cc = n0 + wn * WTN + nt * 8 + 2 * lc;
            float2 v0 = make_float2(c[mt][nt][0], c[mt][nt][1]);
            float2 v1 = make_float2(c[mt][nt][2], c[mt][nt][3]);
            if (TMODE) {
                v0.x = rna_tf32(2.0f * v0.x); v0.y = rna_tf32(2.0f * v0.y);
                v1.x = rna_tf32(2.0f * v1.x); v1.y = rna_tf32(2.0f * v1.y);
            }
            *reinterpret_cast<float2*>(&C[(size_t)r0 * ldc + cc]) = v0;
            *reinterpret_cast<float2*>(&C[(size_t)(r0 + 8) * ldc + cc]) = v1;
        }
    }
}

// ---------------------------------------------------------------------------
// Host
// ---------------------------------------------------------------------------
extern "C" void kernel_launch(void* const* d_in, const int* in_sizes, int n_in,
                              void* d_out, int out_size) {
    const float* x      = (const float*)d_in[0];
    const float* lora_A = (const float*)d_in[1];
    const float* lora_B = (const float*)d_in[2];
    const float* absmax = (const float*)d_in[3];
    const int*   codes  = (const int*)d_in[4];
    float* out = (float*)d_out;

    void *pX, *pW, *pLA;
    cudaGetSymbolAddress(&pX, g_X);
    cudaGetSymbolAddress(&pW, g_W);
    cudaGetSymbolAddress(&pLA, g_LA);

    // main: BM=128 BN=128, 3 stages -> 3*(128+128)*36*4 = 110592 B, 2 CTAs/SM
    constexpr int SMEM_MAIN = 3 * (128 + 128) * 36 * 4;
    // T   : BM=128 BN=64, 3 stages -> 3*(128+64)*36*4 = 82944 B
    constexpr int SMEM_T    = 3 * (128 + 64) * 36 * 4;
    static bool attr_done = false;
    if (!attr_done) {
        cudaFuncSetAttribute((const void*)gemm_mma<128, 128, 2, 4, 3, 2, false, true>,
                             cudaFuncAttributeMaxDynamicSharedMemorySize, SMEM_MAIN);
        cudaFuncSetAttribute((const void*)gemm_mma<128, 64, 4, 2, 3, 2, true, false>,
                             cudaFuncAttributeMaxDynamicSharedMemorySize, SMEM_T);
        attr_done = true;
    }

    // 1) fused prep (one launch)
    prep_kernel<<<3584, 256>>>((const float4*)x, (const float4*)lora_A,
                               (const float4*)lora_B, absmax, codes);

    // 2) T = rna_tf32(2 * x @ lora_A^T)  -> g_X cols 4096..4159
    gemm_mma<128, 64, 4, 2, 3, 2, true, false><<<dim3(1, M_TOTAL / 128), 256, SMEM_T>>>(
        (const float*)pX, KX, (const float*)pLA, IN_DIM,
        (float*)pX + IN_DIM, KX, IN_DIM / 32, 1);

    // 3) out = [x|T] @ [W|loraB]^T   (K = 4160), swizzled 1-D grid, 2 CTAs/SM
    constexpr int NBLK = OUT_DIM / 128;           // 32 n-blocks
    constexpr int MBLK = M_TOTAL / 128;           // 64 m-blocks
    gemm_mma<128, 128, 2, 4, 3, 2, false, true><<<MBLK * NBLK, 256, SMEM_MAIN>>>(
        (const float*)pX, KX, (const float*)pW, KX,
        out, OUT_DIM, KX / 32, NBLK);
}